// round 17
// baseline (speedup 1.0000x reference)
#include <cuda_runtime.h>
#include <cuda_fp16.h>
#include <cstdint>

#define NN 50000
#define EE 800000
#define NPB 128   // nodes per block (resval kernel)
#define FNB 256   // nodes per block (feat kernel)
#define HS_H 72   // h-tile smem stride in halves (144 B)
#define WT_S 72   // transposed-W smem stride in halves

// Scratch (allocation-free rule: __device__ globals)
__device__ __align__(128) __half g_feat[NN * 64];  // 128 B / node = ONE line
__device__ float  g_el[NN * 4];
__device__ float  g_er[NN * 4];
__device__ int    g_idx64;           // 1 if src/dst are int64, 0 if int32

__device__ __forceinline__ uint32_t smem_u32(const void* p)
{
    return (uint32_t)__cvta_generic_to_shared(p);
}

// ---------------------------------------------------------------------------
// Zero kernel: out = 0 (out is poisoned; resval and edge RED-add onto it).
// Also probes index dtype (node ids < 2^31 => int64 encoding has zero high
// words at odd 32-bit slots).
// ---------------------------------------------------------------------------
__global__ __launch_bounds__(256)
void zero_kernel(float4* __restrict__ out4, const unsigned* __restrict__ src_words)
{
    const int i = blockIdx.x * 256 + threadIdx.x;
    if (i == 0) {
        g_idx64 = (src_words[1] == 0u && src_words[3] == 0u &&
                   src_words[5] == 0u && src_words[7] == 0u) ? 1 : 0;
    }
    if (i < NN * 16) out4[i] = make_float4(0.f, 0.f, 0.f, 0.f);
}

// ---------------------------------------------------------------------------
// feat kernel (fp16 tensor cores, ldmatrix-fed): feat = h@W_fc (stored fp16),
// el/er head-dots from the fp32 accumulators. 8 warps, 256 nodes/block.
// ---------------------------------------------------------------------------
__global__ __launch_bounds__(256)
void feat_kernel(const float* __restrict__ h,
                 const float* __restrict__ Wfc,
                 const float* __restrict__ al,
                 const float* __restrict__ ar)
{
    extern __shared__ float smem[];
    __half* hs   = reinterpret_cast<__half*>(smem);           // [256][HS_H]
    __half* Wt   = hs + FNB * HS_H;                           // [64][WT_S]
    float*  al_s = reinterpret_cast<float*>(Wt + 64 * WT_S);  // 64
    float*  ar_s = al_s + 64;                                 // 64

    const int t   = threadIdx.x;
    const int nb0 = blockIdx.x * FNB;

    if (t < 64)       al_s[t]      = al[t];
    else if (t < 128) ar_s[t - 64] = ar[t - 64];

    #pragma unroll
    for (int i = 0; i < 16; i++) {
        const int idx = i * 256 + t;
        const int k = idx >> 6, n = idx & 63;
        Wt[n * WT_S + k] = __float2half(Wfc[idx]);
    }

    {
        const int n = nb0 + t;
        #pragma unroll
        for (int k4 = 0; k4 < 16; k4++) {
            float4 v = make_float4(0.f, 0.f, 0.f, 0.f);
            if (n < NN) v = reinterpret_cast<const float4*>(h)[n * 16 + k4];
            *reinterpret_cast<__half2*>(&hs[t * HS_H + k4 * 4 + 0]) =
                __floats2half2_rn(v.x, v.y);
            *reinterpret_cast<__half2*>(&hs[t * HS_H + k4 * 4 + 2]) =
                __floats2half2_rn(v.z, v.w);
        }
    }
    __syncthreads();

    const int w   = t >> 5;          // 0..7
    const int ln  = t & 31;
    const int gid = ln >> 2;
    const int q   = ln & 3;
    const int rbase = w * 32;

    const int arow_l = ln & 15;
    const int akoff  = (ln >> 4) * 8;
    const int brow_l = ln & 7;
    const int bj     = ln >> 3;
    const int bkoff  = (bj & 1) * 8;
    const int bnsel  = bj >> 1;

    const uint32_t hs_base = smem_u32(hs);
    const uint32_t wt_base = smem_u32(Wt);

    float acc[2][8][4];
    #pragma unroll
    for (int m = 0; m < 2; m++)
        #pragma unroll
        for (int nt = 0; nt < 8; nt++)
            #pragma unroll
            for (int c = 0; c < 4; c++) acc[m][nt][c] = 0.f;

    #pragma unroll
    for (int ks = 0; ks < 4; ks++) {
        const int k0 = ks * 16;
        uint32_t a[2][4];
        #pragma unroll
        for (int m = 0; m < 2; m++) {
            const uint32_t addr = hs_base +
                ((rbase + m * 16 + arow_l) * HS_H + k0 + akoff) * 2;
            asm volatile(
                "ldmatrix.sync.aligned.m8n8.x4.shared.b16 {%0,%1,%2,%3}, [%4];"
                : "=r"(a[m][0]), "=r"(a[m][1]), "=r"(a[m][2]), "=r"(a[m][3])
                : "r"(addr));
        }
        #pragma unroll
        for (int np = 0; np < 4; np++) {
            uint32_t b[4];
            const int nrow = (2 * np + bnsel) * 8 + brow_l;
            const uint32_t baddr = wt_base + (nrow * WT_S + k0 + bkoff) * 2;
            asm volatile(
                "ldmatrix.sync.aligned.m8n8.x4.shared.b16 {%0,%1,%2,%3}, [%4];"
                : "=r"(b[0]), "=r"(b[1]), "=r"(b[2]), "=r"(b[3])
                : "r"(baddr));
            #pragma unroll
            for (int hf = 0; hf < 2; hf++) {
                const int nt = 2 * np + hf;
                #pragma unroll
                for (int m = 0; m < 2; m++) {
                    asm volatile(
                        "mma.sync.aligned.m16n8k16.row.col.f32.f16.f16.f32 "
                        "{%0,%1,%2,%3},{%4,%5,%6,%7},{%8,%9},{%0,%1,%2,%3};"
                        : "+f"(acc[m][nt][0]), "+f"(acc[m][nt][1]),
                          "+f"(acc[m][nt][2]), "+f"(acc[m][nt][3])
                        : "r"(a[m][0]), "r"(a[m][1]), "r"(a[m][2]), "r"(a[m][3]),
                          "r"(b[hf * 2 + 0]), "r"(b[hf * 2 + 1]));
                }
            }
        }
    }

    #pragma unroll
    for (int m = 0; m < 2; m++) {
        #pragma unroll
        for (int half = 0; half < 2; half++) {
            const int n = nb0 + rbase + m * 16 + gid + half * 8;
            float e_l[4] = {0.f, 0.f, 0.f, 0.f};
            float e_r[4] = {0.f, 0.f, 0.f, 0.f};
            #pragma unroll
            for (int nt = 0; nt < 8; nt++) {
                const int hH  = nt >> 1;
                const int c16 = (nt & 1) * 8 + 2 * q;
                const float v0 = acc[m][nt][half * 2 + 0];
                const float v1 = acc[m][nt][half * 2 + 1];
                e_l[hH] += v0 * al_s[hH * 16 + c16] + v1 * al_s[hH * 16 + c16 + 1];
                e_r[hH] += v0 * ar_s[hH * 16 + c16] + v1 * ar_s[hH * 16 + c16 + 1];
            }
            #pragma unroll
            for (int hH = 0; hH < 4; hH++) {
                e_l[hH] += __shfl_xor_sync(0xFFFFFFFFu, e_l[hH], 1);
                e_l[hH] += __shfl_xor_sync(0xFFFFFFFFu, e_l[hH], 2);
                e_r[hH] += __shfl_xor_sync(0xFFFFFFFFu, e_r[hH], 1);
                e_r[hH] += __shfl_xor_sync(0xFFFFFFFFu, e_r[hH], 2);
            }
            if (n < NN) {
                #pragma unroll
                for (int nt = 0; nt < 8; nt++) {
                    const __half2 hv = __floats2half2_rn(acc[m][nt][half * 2 + 0],
                                                         acc[m][nt][half * 2 + 1]);
                    *reinterpret_cast<__half2*>(&g_feat[n * 64 + nt * 8 + 2 * q]) = hv;
                }
                const float ev = (q == 0) ? e_l[0] : (q == 1) ? e_l[1]
                               : (q == 2) ? e_l[2] : e_l[3];
                const float rv = (q == 0) ? e_r[0] : (q == 1) ? e_r[1]
                               : (q == 2) ? e_r[2] : e_r[3];
                g_el[n * 4 + q] = ev;
                g_er[n * 4 + q] = rv;
            }
        }
    }
}

// ---------------------------------------------------------------------------
// resval kernel (fp32 FFMA, off critical path): out += h @ W_res via RED,
// concurrent with edge_kernel's RED accumulation (addition commutes).
// ---------------------------------------------------------------------------
__global__ __launch_bounds__(128, 4)
void resval_kernel(const float* __restrict__ h,
                   const float* __restrict__ Wres,
                   float* __restrict__ out)
{
    extern __shared__ float smem[];
    float* sW = smem;
    float* sT = smem + 4096;

    const int t   = threadIdx.x;
    const int nb0 = blockIdx.x * NPB;

    #pragma unroll
    for (int i = 0; i < 32; i++) sW[i * 128 + t] = Wres[i * 128 + t];

    {
        const int n = nb0 + t;
        #pragma unroll
        for (int k4 = 0; k4 < 16; k4++) {
            float4 v = make_float4(0.f, 0.f, 0.f, 0.f);
            if (n < NN) v = reinterpret_cast<const float4*>(h)[n * 16 + k4];
            sT[(k4 * 4 + 0) * 128 + t] = v.x;
            sT[(k4 * 4 + 1) * 128 + t] = v.y;
            sT[(k4 * 4 + 2) * 128 + t] = v.z;
            sT[(k4 * 4 + 3) * 128 + t] = v.w;
        }
    }
    __syncthreads();

    const int g    = t >> 2;
    const int head = t & 3;

    const float4* sT4 = reinterpret_cast<const float4*>(sT);
    const float4* sW4 = reinterpret_cast<const float4*>(sW);

    float acc[4][16];
    #pragma unroll
    for (int i = 0; i < 4; i++)
        #pragma unroll
        for (int j = 0; j < 16; j++) acc[i][j] = 0.f;

    #pragma unroll 4
    for (int k = 0; k < 64; k++) {
        float4 hv = sT4[k * 32 + g];
        float hvv[4] = {hv.x, hv.y, hv.z, hv.w};
        #pragma unroll
        for (int jq = 0; jq < 4; jq++) {
            float4 wv = sW4[k * 16 + head * 4 + jq];
            #pragma unroll
            for (int i = 0; i < 4; i++) {
                acc[i][jq * 4 + 0] += hvv[i] * wv.x;
                acc[i][jq * 4 + 1] += hvv[i] * wv.y;
                acc[i][jq * 4 + 2] += hvv[i] * wv.z;
                acc[i][jq * 4 + 3] += hvv[i] * wv.w;
            }
        }
    }

    #pragma unroll
    for (int i = 0; i < 4; i++) {
        const int n = nb0 + g * 4 + i;
        if (n < NN) {
            float* op = &out[n * 64 + head * 16];
            #pragma unroll
            for (int jq = 0; jq < 4; jq++) {
                asm volatile("red.global.add.v4.f32 [%0], {%1,%2,%3,%4};"
                             :: "l"(op + jq * 4),
                                "f"(acc[i][jq * 4 + 0]), "f"(acc[i][jq * 4 + 1]),
                                "f"(acc[i][jq * 4 + 2]), "f"(acc[i][jq * 4 + 3])
                             : "memory");
            }
        }
    }
}

// ---------------------------------------------------------------------------
// Edge kernel: 4 threads (one quad) per edge. Head-softmax via quad shuffles.
// Vector phase v2: per step j in {0,1}, lane q loads chunk c=j*4+q as ONE
// uint4 (16 B = dims 8c..8c+8, all of head c>>1) -> the quad covers 64 B and
// the whole 128-B feat record is visited in 2 instructions instead of 4.
// Scatter: 2 v4 REDs per step at o+8c, o+8c+4 (same line pattern as before).
// ---------------------------------------------------------------------------
__global__ __launch_bounds__(256)
void edge_kernel(const void* __restrict__ src_raw,
                 const void* __restrict__ dst_raw,
                 float* __restrict__ out)
{
    const int t = blockIdx.x * 256 + threadIdx.x;
    const int e = t >> 2;
    if (e >= EE) return;
    const int q    = t & 3;
    const int lane = threadIdx.x & 31;

    int s, d;
    if (g_idx64) {
        s = (int)__ldg(&((const long long*)src_raw)[e]);
        d = (int)__ldg(&((const long long*)dst_raw)[e]);
    } else {
        s = __ldg(&((const int*)src_raw)[e]);
        d = __ldg(&((const int*)dst_raw)[e]);
    }

    float x = __ldg(&g_el[s * 4 + q]) + __ldg(&g_er[d * 4 + q]);
    x = (x > 0.f) ? x : 0.2f * x;                       // leaky relu

    float m = x;
    m = fmaxf(m, __shfl_xor_sync(0xFFFFFFFFu, m, 1));
    m = fmaxf(m, __shfl_xor_sync(0xFFFFFFFFu, m, 2));
    const float p = __expf(x - m);
    float ssum = p;
    ssum += __shfl_xor_sync(0xFFFFFFFFu, ssum, 1);
    ssum += __shfl_xor_sync(0xFFFFFFFFu, ssum, 2);
    const float a = p / ssum;        // this lane's head weight

    const uint4* fh = reinterpret_cast<const uint4*>(g_feat + s * 64); // 8x16B
    float*       o  = out + d * 64;
    const int    qb = lane & ~3;

    #pragma unroll
    for (int j = 0; j < 2; j++) {
        const int   c  = j * 4 + q;                       // chunk 0..7
        const float aj = __shfl_sync(0xFFFFFFFFu, a, qb + (c >> 1));
        const uint4 u  = __ldg(&fh[c]);
        const __half2* hh = reinterpret_cast<const __half2*>(&u);
        const float2 f0 = __half22float2(hh[0]);
        const float2 f1 = __half22float2(hh[1]);
        const float2 f2 = __half22float2(hh[2]);
        const float2 f3 = __half22float2(hh[3]);
        asm volatile("red.global.add.v4.f32 [%0], {%1,%2,%3,%4};"
                     :: "l"(o + c * 8),
                        "f"(f0.x * aj), "f"(f0.y * aj), "f"(f1.x * aj), "f"(f1.y * aj)
                     : "memory");
        asm volatile("red.global.add.v4.f32 [%0], {%1,%2,%3,%4};"
                     :: "l"(o + c * 8 + 4),
                        "f"(f2.x * aj), "f"(f2.y * aj), "f"(f3.x * aj), "f"(f3.y * aj)
                     : "memory");
    }
}

// ---------------------------------------------------------------------------
// Schedule:
//   s2 : zero(out,probe) ──► resval (RED into out) ───────[evJoin]
//   s1 : feat(mma,256) ──► [wait evZero] edge ─────────► [wait evJoin]
// ---------------------------------------------------------------------------
extern "C" void kernel_launch(void* const* d_in, const int* in_sizes, int n_in,
                              void* d_out, int out_size)
{
    const float* h    = (const float*)d_in[0];
    const void*  src  = d_in[1];
    const void*  dst  = d_in[2];
    const float* Wfc  = (const float*)d_in[3];
    const float* al   = (const float*)d_in[4];
    const float* ar   = (const float*)d_in[5];
    const float* Wres = (const float*)d_in[6];
    float* out = (float*)d_out;

    const int feat_smem   = (FNB * HS_H + 64 * WT_S) * 2 + 128 * (int)sizeof(float);
    const int resval_smem = (4096 + 64 * NPB) * (int)sizeof(float);

    // One-time host-side resources (no device memory involved).
    static bool         s_init = false;
    static cudaStream_t s2;
    static cudaEvent_t  evFork, evZero, evJoin;
    if (!s_init) {
        cudaStreamCreateWithFlags(&s2, cudaStreamNonBlocking);
        cudaEventCreateWithFlags(&evFork, cudaEventDisableTiming);
        cudaEventCreateWithFlags(&evZero, cudaEventDisableTiming);
        cudaEventCreateWithFlags(&evJoin, cudaEventDisableTiming);
        cudaFuncSetAttribute(feat_kernel,
                             cudaFuncAttributeMaxDynamicSharedMemorySize, feat_smem);
        cudaFuncSetAttribute(resval_kernel,
                             cudaFuncAttributeMaxDynamicSharedMemorySize, resval_smem);
        s_init = true;
    }

    // Fork s2: zero out, then resval RED-adds into it.
    cudaEventRecord(evFork, 0);
    cudaStreamWaitEvent(s2, evFork, 0);
    zero_kernel<<<(NN * 16 + 255) / 256, 256, 0, s2>>>((float4*)out,
                                                       (const unsigned*)src);
    cudaEventRecord(evZero, s2);
    resval_kernel<<<(NN + NPB - 1) / NPB, 128, resval_smem, s2>>>(h, Wres, out);
    cudaEventRecord(evJoin, s2);

    // Main stream: feat, then edge (edge needs feat AND zeroed out).
    feat_kernel<<<(NN + FNB - 1) / FNB, 256, feat_smem>>>(h, Wfc, al, ar);
    cudaStreamWaitEvent(0, evZero, 0);

    const int edge_blocks = (EE * 4) / 256;          // 12500 (exact)
    edge_kernel<<<edge_blocks, 256>>>(src, dst, out);

    // Join: resval must also be complete before the result is read.
    cudaStreamWaitEvent(0, evJoin, 0);
}